// round 7
// baseline (speedup 1.0000x reference)
#include <cuda_runtime.h>
#include <math.h>

#define NB   2
#define NO   512
#define NQ   512
#define NL   256
#define NH   8
#define ND   32
#define NHD  256
#define NOUT 128

// ---------------- scratch (device globals; no allocation allowed) ----------------
__device__ float g_aq[NB * NQ * NL];          // A_q + kb1
__device__ float g_ao[NB * NO * NL];          // A_o
__device__ float g_h1[NB * NO * NL];          // relu(h_obs@fw1+fb1)
__device__ float g_v [NB * NO * NHD];         // value features [b][o][h*32+d]
__device__ float g_logits[NB * NH * NQ * NO]; // [b][h][q][o]
__device__ float g_hq [NB * NQ * NHD];        // v_mean  [b][q][h*32+d]
__device__ float g_var[NB * NQ * NHD];        // variance [b][q][h*32+d]

// ---------------- position projections ----------------
// A_q[row,c] = kb1[c] + sum_i pos_q[i]*(kw1[i][c]+kw1[6+i][c])
// A_o[row,c] =          sum_i pos_o[i]*(kw1[3+i][c]-kw1[6+i][c])
__global__ void __launch_bounds__(NL) k_posproj(const float* __restrict__ pos_obs,
                                                const float* __restrict__ pos_query,
                                                const float* __restrict__ kw1,
                                                const float* __restrict__ kb1) {
    int row = blockIdx.x;
    int c   = threadIdx.x;
    if (row < NB * NQ) {
        const float* p = pos_query + row * 3;
        float acc = kb1[c];
#pragma unroll
        for (int i = 0; i < 3; i++)
            acc = fmaf(p[i], kw1[i * NL + c] + kw1[(6 + i) * NL + c], acc);
        g_aq[row * NL + c] = acc;
    } else {
        int r = row - NB * NQ;
        const float* p = pos_obs + r * 3;
        float acc = 0.f;
#pragma unroll
        for (int i = 0; i < 3; i++)
            acc = fmaf(p[i], kw1[(3 + i) * NL + c] - kw1[(6 + i) * NL + c], acc);
        g_ao[r * NL + c] = acc;
    }
}

// ---------------- generic MLP GEMM: C[M,N] = epi(A[M,256] @ W[256,N] + bias) ----------------
// EPI: 0 = none, 1 = relu, 2 = softplus
template <int N, int ROWS, int EPI>
__global__ void __launch_bounds__(N) k_gemm(const float* __restrict__ A,
                                            const float* __restrict__ W,
                                            const float* __restrict__ bias,
                                            float* __restrict__ C) {
    __shared__ __align__(16) float a_s[ROWS][NL];
    const int tid  = threadIdx.x;
    const int row0 = blockIdx.x * ROWS;
    for (int idx = tid; idx < ROWS * NL; idx += N)
        a_s[idx >> 8][idx & 255] = A[(row0 + (idx >> 8)) * NL + (idx & 255)];
    __syncthreads();

    float acc[ROWS];
#pragma unroll
    for (int r = 0; r < ROWS; r++) acc[r] = 0.f;

    for (int k4 = 0; k4 < NL; k4 += 4) {
        float w0 = W[(k4 + 0) * N + tid];
        float w1 = W[(k4 + 1) * N + tid];
        float w2 = W[(k4 + 2) * N + tid];
        float w3 = W[(k4 + 3) * N + tid];
#pragma unroll
        for (int r = 0; r < ROWS; r++) {
            float4 a = *reinterpret_cast<const float4*>(&a_s[r][k4]);
            acc[r] = fmaf(a.x, w0, acc[r]);
            acc[r] = fmaf(a.y, w1, acc[r]);
            acc[r] = fmaf(a.z, w2, acc[r]);
            acc[r] = fmaf(a.w, w3, acc[r]);
        }
    }
    float bb = bias[tid];
#pragma unroll
    for (int r = 0; r < ROWS; r++) {
        float v = acc[r] + bb;
        if (EPI == 1) v = fmaxf(v, 0.f);
        if (EPI == 2) v = fmaxf(v, 0.f) + log1pf(expf(-fabsf(v)));
        C[(row0 + r) * N + tid] = v;
    }
}

// ---------------- logits: delta MLP + RBF, fused ----------------
// One thread per (q,o) pair in a 16x16 tile. hidden_k = relu(aq_k + ao_k),
// delta[h] += hidden_k * kw2[k][h].
__global__ void __launch_bounds__(256) k_logits(const float* __restrict__ pos_obs,
                                                const float* __restrict__ pos_query,
                                                const float* __restrict__ kw2,
                                                const float* __restrict__ kb2,
                                                const float* __restrict__ log_sigma) {
    __shared__ __align__(16) float kw2_s[NL * NH];   // 8 KB
    __shared__ float aq_s[NL * 17];                  // [k][ql], pitch 17 (17 KB)
    __shared__ float ao_s[NL * 17];                  // [k][ol], pitch 17 (17 KB)
    __shared__ float pq_s[16][3], po_s[16][3];
    __shared__ float inv_s2[NH], kb2_s[NH];

    const int tid = threadIdx.x;
    const int o0  = blockIdx.x * 16;
    const int q0  = blockIdx.y * 16;
    const int b   = blockIdx.z;

    for (int idx = tid; idx < NL * NH; idx += 256) kw2_s[idx] = kw2[idx];
    for (int idx = tid; idx < 16 * NL; idx += 256) {
        int r = idx >> 8, k = idx & 255;
        aq_s[k * 17 + r] = g_aq[(b * NQ + q0 + r) * NL + k];
        ao_s[k * 17 + r] = g_ao[(b * NO + o0 + r) * NL + k];
    }
    if (tid < 48) {
        pq_s[tid / 3][tid % 3] = pos_query[(b * NQ + q0) * 3 + tid];
    } else if (tid < 96) {
        int t = tid - 48;
        po_s[t / 3][t % 3] = pos_obs[(b * NO + o0) * 3 + t];
    } else if (tid < 104) {
        int h = tid - 96;
        float s   = expf(log_sigma[h]);
        inv_s2[h] = 1.f / (s * s + 1e-6f);
        kb2_s[h]  = kb2[h];
    }
    __syncthreads();

    const int ol = tid & 15, ql = tid >> 4;
    float acc[8];
#pragma unroll
    for (int h = 0; h < 8; h++) acc[h] = 0.f;

#pragma unroll 4
    for (int k = 0; k < NL; k++) {
        float a   = aq_s[k * 17 + ql];   // broadcast within warp (2 distinct)
        float oo  = ao_s[k * 17 + ol];   // 16 consecutive words, conflict-free
        float hkv = fmaxf(a + oo, 0.f);
        const float4* wp = reinterpret_cast<const float4*>(kw2_s + k * 8);
        float4 w0 = wp[0], w1 = wp[1];   // broadcast (same address all lanes)
        acc[0] = fmaf(hkv, w0.x, acc[0]);
        acc[1] = fmaf(hkv, w0.y, acc[1]);
        acc[2] = fmaf(hkv, w0.z, acc[2]);
        acc[3] = fmaf(hkv, w0.w, acc[3]);
        acc[4] = fmaf(hkv, w1.x, acc[4]);
        acc[5] = fmaf(hkv, w1.y, acc[5]);
        acc[6] = fmaf(hkv, w1.z, acc[6]);
        acc[7] = fmaf(hkv, w1.w, acc[7]);
    }

    float dx = pq_s[ql][0] - po_s[ol][0];
    float dy = pq_s[ql][1] - po_s[ol][1];
    float dz = pq_s[ql][2] - po_s[ol][2];
    float dist2 = dx * dx + dy * dy + dz * dz;

    const int q = q0 + ql, o = o0 + ol;
    float* outp = g_logits + ((size_t)(b * NH) * NQ + q) * NO + o;
#pragma unroll
    for (int h = 0; h < NH; h++) {
        float t  = -dist2 * inv_s2[h];
        float lg = logf(expf(t) + 1e-8f) + acc[h] + kb2_s[h];
        outp[(size_t)h * NQ * NO] = lg;
    }
}

// ---------------- softmax + weighted mean/var ----------------
// One CTA per (b,h,q-tile of 16). Phase 1: row softmax into smem.
// Phase 2: mean = W@v, E2 = W@v^2, var = E2 - mean^2 (sum w == 1).
__global__ void __launch_bounds__(256) k_attn() {
    __shared__ float w_s[16][NO];    // 32 KB
    const int bid = blockIdx.x;
    const int qt = bid & 31, h = (bid >> 5) & 7, b = bid >> 8;
    const int q0 = qt * 16;
    const int tid = threadIdx.x, lane = tid & 31, warp = tid >> 5;

    const float* lbase = g_logits + (size_t)(b * NH + h) * NQ * NO;
    for (int r = warp; r < 16; r += 8) {
        const float* lp = lbase + (size_t)(q0 + r) * NO;
        float vals[16];
        float mx = -3.0e38f;
#pragma unroll
        for (int j = 0; j < 16; j++) {
            vals[j] = lp[lane + j * 32];
            mx = fmaxf(mx, vals[j]);
        }
#pragma unroll
        for (int s = 16; s > 0; s >>= 1) mx = fmaxf(mx, __shfl_xor_sync(0xffffffffu, mx, s));
        float sum = 0.f;
#pragma unroll
        for (int j = 0; j < 16; j++) { vals[j] = expf(vals[j] - mx); sum += vals[j]; }
#pragma unroll
        for (int s = 16; s > 0; s >>= 1) sum += __shfl_xor_sync(0xffffffffu, sum, s);
        float inv = 1.f / sum;
#pragma unroll
        for (int j = 0; j < 16; j++) w_s[r][lane + j * 32] = vals[j] * inv;
    }
    __syncthreads();

    const int d = tid & 31, qq = tid >> 5;  // qq in 0..7, handles rows qq and qq+8
    const float* vp = g_v + (size_t)(b * NO) * NHD + h * ND + d;
    float m1 = 0.f, e1 = 0.f, m2 = 0.f, e2 = 0.f;
#pragma unroll 4
    for (int o = 0; o < NO; o++) {
        float v  = __ldg(vp + (size_t)o * NHD);  // 128B/warp, L1-resident across warps
        float v2 = v * v;
        float wa = w_s[qq][o];       // broadcast
        float wb = w_s[qq + 8][o];   // broadcast
        m1 = fmaf(wa, v, m1);  e1 = fmaf(wa, v2, e1);
        m2 = fmaf(wb, v, m2);  e2 = fmaf(wb, v2, e2);
    }
    size_t base = (size_t)(b * NQ + q0) * NHD + h * ND + d;
    g_hq [base + (size_t)qq * NHD]       = m1;
    g_var[base + (size_t)qq * NHD]       = e1 - m1 * m1;
    g_hq [base + (size_t)(qq + 8) * NHD] = m2;
    g_var[base + (size_t)(qq + 8) * NHD] = e2 - m2 * m2;
}

// ---------------- launcher ----------------
extern "C" void kernel_launch(void* const* d_in, const int* in_sizes, int n_in,
                              void* d_out, int out_size) {
    const float* h_obs     = (const float*)d_in[0];
    const float* pos_obs   = (const float*)d_in[1];
    const float* pos_query = (const float*)d_in[2];
    const float* fw1       = (const float*)d_in[3];
    const float* fb1       = (const float*)d_in[4];
    const float* fw2       = (const float*)d_in[5];
    const float* fb2       = (const float*)d_in[6];
    const float* log_sigma = (const float*)d_in[7];
    const float* kw1       = (const float*)d_in[8];
    const float* kb1       = (const float*)d_in[9];
    const float* kw2       = (const float*)d_in[10];
    const float* kb2       = (const float*)d_in[11];
    const float* ow        = (const float*)d_in[12];
    const float* ob        = (const float*)d_in[13];
    const float* vw        = (const float*)d_in[14];
    const float* vb        = (const float*)d_in[15];
    float* out = (float*)d_out;

    float *p_h1, *p_v, *p_hq, *p_var;
    cudaGetSymbolAddress((void**)&p_h1,  g_h1);
    cudaGetSymbolAddress((void**)&p_v,   g_v);
    cudaGetSymbolAddress((void**)&p_hq,  g_hq);
    cudaGetSymbolAddress((void**)&p_var, g_var);

    // position projections for the factored key-MLP
    k_posproj<<<NB * (NQ + NO), NL>>>(pos_obs, pos_query, kw1, kb1);

    // value MLP: v = relu(h_obs@fw1+fb1)@fw2+fb2
    k_gemm<256, 8, 1><<<NB * NO / 8, 256>>>(h_obs, fw1, fb1, p_h1);
    k_gemm<256, 8, 0><<<NB * NO / 8, 256>>>(p_h1, fw2, fb2, p_v);

    // logits = log(rbf+1e-8) + delta
    dim3 glog(NO / 16, NQ / 16, NB);
    k_logits<<<glog, 256>>>(pos_obs, pos_query, kw2, kb2, log_sigma);

    // softmax + weighted mean / variance
    k_attn<<<NB * NH * (NQ / 16), 256>>>();

    // outputs: mean = hq@ow+ob ; var_out = softplus(var@vw+vb)
    k_gemm<128, 8, 0><<<NB * NQ / 8, 128>>>(p_hq, ow, ob, out);
    k_gemm<128, 8, 2><<<NB * NQ / 8, 128>>>(p_var, vw, vb, out + NB * NQ * NOUT);
}

// round 9
// speedup vs baseline: 1.0181x; 1.0181x over previous
#include <cuda_runtime.h>
#include <math.h>

#define NB   2
#define NO   512
#define NQ   512
#define NL   256
#define NH   8
#define ND   32
#define NHD  256
#define NOUT 128

// ---------------- scratch (device globals; no allocation allowed) ----------------
__device__ float g_aq[NB * NQ * NL];          // A_q + kb1
__device__ float g_ao[NB * NO * NL];          // A_o
__device__ float g_h1[NB * NO * NL];          // relu(h_obs@fw1+fb1)
__device__ float g_v [NB * NO * NHD];         // value features [b][o][h*32+d]
__device__ float g_logits[NB * NH * NQ * NO]; // [b][h][q][o]
__device__ float g_hq [NB * NQ * NHD];        // v_mean  [b][q][h*32+d]
__device__ float g_var[NB * NQ * NHD];        // variance [b][q][h*32+d]

// ---------------- position projections ----------------
// A_q[row,c] = kb1[c] + sum_i pos_q[i]*(kw1[i][c]+kw1[6+i][c])
// A_o[row,c] =          sum_i pos_o[i]*(kw1[3+i][c]-kw1[6+i][c])
__global__ void __launch_bounds__(NL) k_posproj(const float* __restrict__ pos_obs,
                                                const float* __restrict__ pos_query,
                                                const float* __restrict__ kw1,
                                                const float* __restrict__ kb1) {
    int row = blockIdx.x;
    int c   = threadIdx.x;
    if (row < NB * NQ) {
        const float* p = pos_query + row * 3;
        float acc = kb1[c];
#pragma unroll
        for (int i = 0; i < 3; i++)
            acc = fmaf(p[i], kw1[i * NL + c] + kw1[(6 + i) * NL + c], acc);
        g_aq[row * NL + c] = acc;
    } else {
        int r = row - NB * NQ;
        const float* p = pos_obs + r * 3;
        float acc = 0.f;
#pragma unroll
        for (int i = 0; i < 3; i++)
            acc = fmaf(p[i], kw1[(3 + i) * NL + c] - kw1[(6 + i) * NL + c], acc);
        g_ao[r * NL + c] = acc;
    }
}

// ---------------- generic MLP GEMM: C[M,N] = epi(A[M,256] @ W[256,N] + bias) ----------------
// EPI: 0 = none, 1 = relu, 2 = softplus
template <int N, int ROWS, int EPI>
__global__ void __launch_bounds__(N) k_gemm(const float* __restrict__ A,
                                            const float* __restrict__ W,
                                            const float* __restrict__ bias,
                                            float* __restrict__ C) {
    __shared__ __align__(16) float a_s[ROWS][NL];
    const int tid  = threadIdx.x;
    const int row0 = blockIdx.x * ROWS;
    for (int idx = tid; idx < ROWS * NL; idx += N)
        a_s[idx >> 8][idx & 255] = A[(row0 + (idx >> 8)) * NL + (idx & 255)];
    __syncthreads();

    float acc[ROWS];
#pragma unroll
    for (int r = 0; r < ROWS; r++) acc[r] = 0.f;

    for (int k4 = 0; k4 < NL; k4 += 4) {
        float w0 = W[(k4 + 0) * N + tid];
        float w1 = W[(k4 + 1) * N + tid];
        float w2 = W[(k4 + 2) * N + tid];
        float w3 = W[(k4 + 3) * N + tid];
#pragma unroll
        for (int r = 0; r < ROWS; r++) {
            float4 a = *reinterpret_cast<const float4*>(&a_s[r][k4]);
            acc[r] = fmaf(a.x, w0, acc[r]);
            acc[r] = fmaf(a.y, w1, acc[r]);
            acc[r] = fmaf(a.z, w2, acc[r]);
            acc[r] = fmaf(a.w, w3, acc[r]);
        }
    }
    float bb = bias[tid];
#pragma unroll
    for (int r = 0; r < ROWS; r++) {
        float v = acc[r] + bb;
        if (EPI == 1) v = fmaxf(v, 0.f);
        if (EPI == 2) v = fmaxf(v, 0.f) + log1pf(expf(-fabsf(v)));
        C[(row0 + r) * N + tid] = v;
    }
}

// ---------------- logits: delta MLP + RBF, fused ----------------
// One thread per (q,o) pair in a 16x16 tile. hidden_k = relu(aq_k + ao_k),
// delta[h] += hidden_k * kw2[k][h].
__global__ void __launch_bounds__(256) k_logits(const float* __restrict__ pos_obs,
                                                const float* __restrict__ pos_query,
                                                const float* __restrict__ kw2,
                                                const float* __restrict__ kb2,
                                                const float* __restrict__ log_sigma) {
    __shared__ __align__(16) float kw2_s[NL * NH];   // 8 KB
    __shared__ float aq_s[NL * 17];                  // [k][ql], pitch 17 (17 KB)
    __shared__ float ao_s[NL * 17];                  // [k][ol], pitch 17 (17 KB)
    __shared__ float pq_s[16][3], po_s[16][3];
    __shared__ float inv_s2[NH], kb2_s[NH];

    const int tid = threadIdx.x;
    const int o0  = blockIdx.x * 16;
    const int q0  = blockIdx.y * 16;
    const int b   = blockIdx.z;

    for (int idx = tid; idx < NL * NH; idx += 256) kw2_s[idx] = kw2[idx];
    for (int idx = tid; idx < 16 * NL; idx += 256) {
        int r = idx >> 8, k = idx & 255;
        aq_s[k * 17 + r] = g_aq[(b * NQ + q0 + r) * NL + k];
        ao_s[k * 17 + r] = g_ao[(b * NO + o0 + r) * NL + k];
    }
    if (tid < 48) {
        pq_s[tid / 3][tid % 3] = pos_query[(b * NQ + q0) * 3 + tid];
    } else if (tid < 96) {
        int t = tid - 48;
        po_s[t / 3][t % 3] = pos_obs[(b * NO + o0) * 3 + t];
    } else if (tid < 104) {
        int h = tid - 96;
        float s   = expf(log_sigma[h]);
        inv_s2[h] = 1.f / (s * s + 1e-6f);
        kb2_s[h]  = kb2[h];
    }
    __syncthreads();

    const int ol = tid & 15, ql = tid >> 4;
    float acc[8];
#pragma unroll
    for (int h = 0; h < 8; h++) acc[h] = 0.f;

#pragma unroll 4
    for (int k = 0; k < NL; k++) {
        float a   = aq_s[k * 17 + ql];   // broadcast within warp (2 distinct)
        float oo  = ao_s[k * 17 + ol];   // 16 consecutive words, conflict-free
        float hkv = fmaxf(a + oo, 0.f);
        const float4* wp = reinterpret_cast<const float4*>(kw2_s + k * 8);
        float4 w0 = wp[0], w1 = wp[1];   // broadcast (same address all lanes)
        acc[0] = fmaf(hkv, w0.x, acc[0]);
        acc[1] = fmaf(hkv, w0.y, acc[1]);
        acc[2] = fmaf(hkv, w0.z, acc[2]);
        acc[3] = fmaf(hkv, w0.w, acc[3]);
        acc[4] = fmaf(hkv, w1.x, acc[4]);
        acc[5] = fmaf(hkv, w1.y, acc[5]);
        acc[6] = fmaf(hkv, w1.z, acc[6]);
        acc[7] = fmaf(hkv, w1.w, acc[7]);
    }

    float dx = pq_s[ql][0] - po_s[ol][0];
    float dy = pq_s[ql][1] - po_s[ol][1];
    float dz = pq_s[ql][2] - po_s[ol][2];
    float dist2 = dx * dx + dy * dy + dz * dz;

    const int q = q0 + ql, o = o0 + ol;
    float* outp = g_logits + ((size_t)(b * NH) * NQ + q) * NO + o;
#pragma unroll
    for (int h = 0; h < NH; h++) {
        float t  = -dist2 * inv_s2[h];
        float lg = logf(expf(t) + 1e-8f) + acc[h] + kb2_s[h];
        outp[(size_t)h * NQ * NO] = lg;
    }
}

// ---------------- softmax + weighted mean/var ----------------
// One CTA per (b,h,q-tile of 16). Phase 1: row softmax into smem.
// Phase 2: mean = W@v, E2 = W@v^2, var = E2 - mean^2 (sum w == 1).
__global__ void __launch_bounds__(256) k_attn() {
    __shared__ float w_s[16][NO];    // 32 KB
    const int bid = blockIdx.x;
    const int qt = bid & 31, h = (bid >> 5) & 7, b = bid >> 8;
    const int q0 = qt * 16;
    const int tid = threadIdx.x, lane = tid & 31, warp = tid >> 5;

    const float* lbase = g_logits + (size_t)(b * NH + h) * NQ * NO;
    for (int r = warp; r < 16; r += 8) {
        const float* lp = lbase + (size_t)(q0 + r) * NO;
        float vals[16];
        float mx = -3.0e38f;
#pragma unroll
        for (int j = 0; j < 16; j++) {
            vals[j] = lp[lane + j * 32];
            mx = fmaxf(mx, vals[j]);
        }
#pragma unroll
        for (int s = 16; s > 0; s >>= 1) mx = fmaxf(mx, __shfl_xor_sync(0xffffffffu, mx, s));
        float sum = 0.f;
#pragma unroll
        for (int j = 0; j < 16; j++) { vals[j] = expf(vals[j] - mx); sum += vals[j]; }
#pragma unroll
        for (int s = 16; s > 0; s >>= 1) sum += __shfl_xor_sync(0xffffffffu, sum, s);
        float inv = 1.f / sum;
#pragma unroll
        for (int j = 0; j < 16; j++) w_s[r][lane + j * 32] = vals[j] * inv;
    }
    __syncthreads();

    const int d = tid & 31, qq = tid >> 5;  // qq in 0..7, handles rows qq and qq+8
    const float* vp = g_v + (size_t)(b * NO) * NHD + h * ND + d;
    float m1 = 0.f, e1 = 0.f, m2 = 0.f, e2 = 0.f;
#pragma unroll 4
    for (int o = 0; o < NO; o++) {
        float v  = __ldg(vp + (size_t)o * NHD);  // 128B/warp, L1-resident across warps
        float v2 = v * v;
        float wa = w_s[qq][o];       // broadcast
        float wb = w_s[qq + 8][o];   // broadcast
        m1 = fmaf(wa, v, m1);  e1 = fmaf(wa, v2, e1);
        m2 = fmaf(wb, v, m2);  e2 = fmaf(wb, v2, e2);
    }
    size_t base = (size_t)(b * NQ + q0) * NHD + h * ND + d;
    g_hq [base + (size_t)qq * NHD]       = m1;
    g_var[base + (size_t)qq * NHD]       = e1 - m1 * m1;
    g_hq [base + (size_t)(qq + 8) * NHD] = m2;
    g_var[base + (size_t)(qq + 8) * NHD] = e2 - m2 * m2;
}

// ---------------- launcher ----------------
extern "C" void kernel_launch(void* const* d_in, const int* in_sizes, int n_in,
                              void* d_out, int out_size) {
    const float* h_obs     = (const float*)d_in[0];
    const float* pos_obs   = (const float*)d_in[1];
    const float* pos_query = (const float*)d_in[2];
    const float* fw1       = (const float*)d_in[3];
    const float* fb1       = (const float*)d_in[4];
    const float* fw2       = (const float*)d_in[5];
    const float* fb2       = (const float*)d_in[6];
    const float* log_sigma = (const float*)d_in[7];
    const float* kw1       = (const float*)d_in[8];
    const float* kb1       = (const float*)d_in[9];
    const float* kw2       = (const float*)d_in[10];
    const float* kb2       = (const float*)d_in[11];
    const float* ow        = (const float*)d_in[12];
    const float* ob        = (const float*)d_in[13];
    const float* vw        = (const float*)d_in[14];
    const float* vb        = (const float*)d_in[15];
    float* out = (float*)d_out;

    float *p_h1, *p_v, *p_hq, *p_var;
    cudaGetSymbolAddress((void**)&p_h1,  g_h1);
    cudaGetSymbolAddress((void**)&p_v,   g_v);
    cudaGetSymbolAddress((void**)&p_hq,  g_hq);
    cudaGetSymbolAddress((void**)&p_var, g_var);

    // position projections for the factored key-MLP
    k_posproj<<<NB * (NQ + NO), NL>>>(pos_obs, pos_query, kw1, kb1);

    // value MLP: v = relu(h_obs@fw1+fb1)@fw2+fb2
    k_gemm<256, 8, 1><<<NB * NO / 8, 256>>>(h_obs, fw1, fb1, p_h1);
    k_gemm<256, 8, 0><<<NB * NO / 8, 256>>>(p_h1, fw2, fb2, p_v);

    // logits = log(rbf+1e-8) + delta
    dim3 glog(NO / 16, NQ / 16, NB);
    k_logits<<<glog, 256>>>(pos_obs, pos_query, kw2, kb2, log_sigma);

    // softmax + weighted mean / variance
    k_attn<<<NB * NH * (NQ / 16), 256>>>();

    // outputs: mean = hq@ow+ob ; var_out = softplus(var@vw+vb)
    k_gemm<128, 8, 0><<<NB * NQ / 8, 128>>>(p_hq, ow, ob, out);
    k_gemm<128, 8, 2><<<NB * NQ / 8, 128>>>(p_var, vw, vb, out + NB * NQ * NOUT);
}

// round 10
// speedup vs baseline: 1.3761x; 1.3516x over previous
#include <cuda_runtime.h>
#include <math.h>

#define NB   2
#define NO   512
#define NQ   512
#define NL   256
#define NH   8
#define ND   32
#define NHD  256
#define NOUT 128
#define KC   64

typedef unsigned long long u64;

__device__ __forceinline__ u64 pack_dup(float x) {
    u64 r; asm("mov.b64 %0, {%1, %1};" : "=l"(r) : "f"(x)); return r;
}
__device__ __forceinline__ void fma2(u64 &d, u64 a, u64 b) {
    asm("fma.rn.f32x2 %0, %1, %2, %0;" : "+l"(d) : "l"(a), "l"(b));
}
__device__ __forceinline__ float2 unpack2(u64 v) {
    float2 r; asm("mov.b64 {%0, %1}, %2;" : "=f"(r.x), "=f"(r.y) : "l"(v)); return r;
}

// ---------------- scratch (device globals; no allocation allowed) ----------------
__device__ float g_aq[NB * NQ * NL];          // A_q + kb1
__device__ float g_ao[NB * NO * NL];          // A_o
__device__ float g_h1[NB * NO * NL];          // relu(h_obs@fw1+fb1)
__device__ float g_v [NB * NO * NHD];         // value features [b][o][h*32+d]
__device__ float g_logits[NB * NH * NQ * NO]; // [b][h][q][o]
__device__ float g_hq [NB * NQ * NHD];        // v_mean  [b][q][h*32+d]
__device__ float g_var[NB * NQ * NHD];        // variance [b][q][h*32+d]

// ---------------- position projections ----------------
__global__ void __launch_bounds__(NL) k_posproj(const float* __restrict__ pos_obs,
                                                const float* __restrict__ pos_query,
                                                const float* __restrict__ kw1,
                                                const float* __restrict__ kb1) {
    int row = blockIdx.x;
    int c   = threadIdx.x;
    if (row < NB * NQ) {
        const float* p = pos_query + row * 3;
        float acc = kb1[c];
#pragma unroll
        for (int i = 0; i < 3; i++)
            acc = fmaf(p[i], kw1[i * NL + c] + kw1[(6 + i) * NL + c], acc);
        g_aq[row * NL + c] = acc;
    } else {
        int r = row - NB * NQ;
        const float* p = pos_obs + r * 3;
        float acc = 0.f;
#pragma unroll
        for (int i = 0; i < 3; i++)
            acc = fmaf(p[i], kw1[(3 + i) * NL + c] - kw1[(6 + i) * NL + c], acc);
        g_ao[r * NL + c] = acc;
    }
}

// ---------------- generic MLP GEMM: C[M,N] = epi(A[M,256] @ W[256,N] + bias) ----------------
template <int N, int ROWS, int EPI>
__global__ void __launch_bounds__(N) k_gemm(const float* __restrict__ A,
                                            const float* __restrict__ W,
                                            const float* __restrict__ bias,
                                            float* __restrict__ C) {
    __shared__ __align__(16) float a_s[ROWS][NL];
    const int tid  = threadIdx.x;
    const int row0 = blockIdx.x * ROWS;
    for (int idx = tid; idx < ROWS * NL; idx += N)
        a_s[idx >> 8][idx & 255] = A[(row0 + (idx >> 8)) * NL + (idx & 255)];
    __syncthreads();

    float acc[ROWS];
#pragma unroll
    for (int r = 0; r < ROWS; r++) acc[r] = 0.f;

    for (int k4 = 0; k4 < NL; k4 += 4) {
        float w0 = W[(k4 + 0) * N + tid];
        float w1 = W[(k4 + 1) * N + tid];
        float w2 = W[(k4 + 2) * N + tid];
        float w3 = W[(k4 + 3) * N + tid];
#pragma unroll
        for (int r = 0; r < ROWS; r++) {
            float4 a = *reinterpret_cast<const float4*>(&a_s[r][k4]);
            acc[r] = fmaf(a.x, w0, acc[r]);
            acc[r] = fmaf(a.y, w1, acc[r]);
            acc[r] = fmaf(a.z, w2, acc[r]);
            acc[r] = fmaf(a.w, w3, acc[r]);
        }
    }
    float bb = bias[tid];
#pragma unroll
    for (int r = 0; r < ROWS; r++) {
        float v = acc[r] + bb;
        if (EPI == 1) v = fmaxf(v, 0.f);
        if (EPI == 2) v = fmaxf(v, 0.f) + log1pf(expf(-fabsf(v)));
        C[(row0 + r) * N + tid] = v;
    }
}

// ---------------- fused output heads: mean = hq@ow+ob ; var_out = softplus(var@vw+vb) ----------------
__global__ void __launch_bounds__(NOUT) k_out(const float* __restrict__ hq,
                                              const float* __restrict__ var,
                                              const float* __restrict__ ow,
                                              const float* __restrict__ ob,
                                              const float* __restrict__ vw,
                                              const float* __restrict__ vb,
                                              float* __restrict__ out) {
    __shared__ __align__(16) float a_s[8][NL];
    const int tid  = threadIdx.x;
    const int row0 = blockIdx.x * 8;
    const int sel  = blockIdx.y;
    const float* A    = sel ? var : hq;
    const float* W    = sel ? vw  : ow;
    const float* bias = sel ? vb  : ob;
    float* C = out + (sel ? (size_t)NB * NQ * NOUT : 0);

    for (int idx = tid; idx < 8 * NL; idx += NOUT)
        a_s[idx >> 8][idx & 255] = A[(row0 + (idx >> 8)) * NL + (idx & 255)];
    __syncthreads();

    float acc[8];
#pragma unroll
    for (int r = 0; r < 8; r++) acc[r] = 0.f;

    for (int k4 = 0; k4 < NL; k4 += 4) {
        float w0 = W[(k4 + 0) * NOUT + tid];
        float w1 = W[(k4 + 1) * NOUT + tid];
        float w2 = W[(k4 + 2) * NOUT + tid];
        float w3 = W[(k4 + 3) * NOUT + tid];
#pragma unroll
        for (int r = 0; r < 8; r++) {
            float4 a = *reinterpret_cast<const float4*>(&a_s[r][k4]);
            acc[r] = fmaf(a.x, w0, acc[r]);
            acc[r] = fmaf(a.y, w1, acc[r]);
            acc[r] = fmaf(a.z, w2, acc[r]);
            acc[r] = fmaf(a.w, w3, acc[r]);
        }
    }
    float bb = bias[tid];
#pragma unroll
    for (int r = 0; r < 8; r++) {
        float v = acc[r] + bb;
        if (sel) v = fmaxf(v, 0.f) + log1pf(expf(-fabsf(v)));
        C[(row0 + r) * NOUT + tid] = v;
    }
}

// ---------------- logits: delta MLP + RBF, fused (2x2 reg tile + f32x2 head packing) ----------------
// Block tile 32q x 32o, 256 threads, each thread: 2q x 2o pairs, 8 heads as 4 f32x2 accumulators.
__global__ void __launch_bounds__(256) k_logits(const float* __restrict__ pos_obs,
                                                const float* __restrict__ pos_query,
                                                const float* __restrict__ kw2,
                                                const float* __restrict__ kb2,
                                                const float* __restrict__ log_sigma) {
    __shared__ __align__(16) float kw2_s[NL * NH];   // 8 KB
    __shared__ float aq_s[KC * 34];                  // [kk][q], pitch 34 (even, conflict-light)
    __shared__ float ao_s[KC * 34];                  // [kk][o]
    __shared__ float pq_s[32][3], po_s[32][3];
    __shared__ float inv_s2[NH], kb2_s[NH];

    const int tid = threadIdx.x;
    const int o0  = blockIdx.x * 32;
    const int q0  = blockIdx.y * 32;
    const int b   = blockIdx.z;
    const int ol  = tid & 15;     // o pair index: o = o0 + 2*ol + {0,1}
    const int ql  = tid >> 4;     // q pair index: q = q0 + 2*ql + {0,1}

    for (int idx = tid; idx < NL * NH; idx += 256) kw2_s[idx] = kw2[idx];
    if (tid < 96) {
        pq_s[tid / 3][tid % 3] = pos_query[(b * NQ + q0) * 3 + tid];
    } else if (tid < 192) {
        int t = tid - 96;
        po_s[t / 3][t % 3] = pos_obs[(b * NO + o0) * 3 + t];
    } else if (tid < 200) {
        int h = tid - 192;
        float s   = expf(log_sigma[h]);
        inv_s2[h] = 1.f / (s * s + 1e-6f);
        kb2_s[h]  = kb2[h];
    }

    u64 acc[4][4];   // [pair: q0o0,q0o1,q1o0,q1o1][head-pair]
#pragma unroll
    for (int p = 0; p < 4; p++)
#pragma unroll
        for (int j = 0; j < 4; j++) acc[p][j] = 0ULL;

    const float* aqg = g_aq + (size_t)(b * NQ + q0) * NL;
    const float* aog = g_ao + (size_t)(b * NO + o0) * NL;

    for (int kc = 0; kc < NL; kc += KC) {
        __syncthreads();
        // stage chunk: aq_s[kk][qq], ao_s[kk][oo], coalesced gmem float2 reads
        for (int idx = tid; idx < (KC / 2) * 32; idx += 256) {
            int kk2 = (idx & 31) * 2, rr = idx >> 5;
            float2 va = *reinterpret_cast<const float2*>(aqg + rr * NL + kc + kk2);
            aq_s[kk2 * 34 + rr]       = va.x;
            aq_s[(kk2 + 1) * 34 + rr] = va.y;
            float2 vo = *reinterpret_cast<const float2*>(aog + rr * NL + kc + kk2);
            ao_s[kk2 * 34 + rr]       = vo.x;
            ao_s[(kk2 + 1) * 34 + rr] = vo.y;
        }
        __syncthreads();

#pragma unroll 4
        for (int kk = 0; kk < KC; kk++) {
            float2 aq2 = *reinterpret_cast<const float2*>(&aq_s[kk * 34 + 2 * ql]);
            float2 ao2 = *reinterpret_cast<const float2*>(&ao_s[kk * 34 + 2 * ol]);
            float h00 = fmaxf(aq2.x + ao2.x, 0.f);
            float h01 = fmaxf(aq2.x + ao2.y, 0.f);
            float h10 = fmaxf(aq2.y + ao2.x, 0.f);
            float h11 = fmaxf(aq2.y + ao2.y, 0.f);
            u64 d00 = pack_dup(h00), d01 = pack_dup(h01);
            u64 d10 = pack_dup(h10), d11 = pack_dup(h11);
            const ulonglong2* wp = reinterpret_cast<const ulonglong2*>(kw2_s + (kc + kk) * 8);
            ulonglong2 wA = wp[0], wB = wp[1];  // wA.x={h0,h1} wA.y={h2,h3} wB.x={h4,h5} wB.y={h6,h7}
            fma2(acc[0][0], d00, wA.x); fma2(acc[0][1], d00, wA.y);
            fma2(acc[0][2], d00, wB.x); fma2(acc[0][3], d00, wB.y);
            fma2(acc[1][0], d01, wA.x); fma2(acc[1][1], d01, wA.y);
            fma2(acc[1][2], d01, wB.x); fma2(acc[1][3], d01, wB.y);
            fma2(acc[2][0], d10, wA.x); fma2(acc[2][1], d10, wA.y);
            fma2(acc[2][2], d10, wB.x); fma2(acc[2][3], d10, wB.y);
            fma2(acc[3][0], d11, wA.x); fma2(acc[3][1], d11, wA.y);
            fma2(acc[3][2], d11, wB.x); fma2(acc[3][3], d11, wB.y);
        }
    }

    const int oA = o0 + 2 * ol;
    const float pax = po_s[2 * ol][0],     pay = po_s[2 * ol][1],     paz = po_s[2 * ol][2];
    const float pbx = po_s[2 * ol + 1][0], pby = po_s[2 * ol + 1][1], pbz = po_s[2 * ol + 1][2];

#pragma unroll
    for (int qi = 0; qi < 2; qi++) {
        int q = q0 + 2 * ql + qi;
        float px = pq_s[2 * ql + qi][0], py = pq_s[2 * ql + qi][1], pz = pq_s[2 * ql + qi][2];
        float dxA = px - pax, dyA = py - pay, dzA = pz - paz;
        float dxB = px - pbx, dyB = py - pby, dzB = pz - pbz;
        float d2A = dxA * dxA + dyA * dyA + dzA * dzA;
        float d2B = dxB * dxB + dyB * dyB + dzB * dzB;
        float* orow = g_logits + ((size_t)(b * NH) * NQ + q) * NO + oA;
#pragma unroll
        for (int hp = 0; hp < 4; hp++) {
            float2 vA = unpack2(acc[qi * 2 + 0][hp]);   // o = oA,   heads {2hp, 2hp+1}
            float2 vB = unpack2(acc[qi * 2 + 1][hp]);   // o = oA+1
#pragma unroll
            for (int hl = 0; hl < 2; hl++) {
                int h = 2 * hp + hl;
                float va  = hl ? vA.y : vA.x;
                float vbb = hl ? vB.y : vB.x;
                float lgA = logf(expf(-d2A * inv_s2[h]) + 1e-8f) + va  + kb2_s[h];
                float lgB = logf(expf(-d2B * inv_s2[h]) + 1e-8f) + vbb + kb2_s[h];
                *reinterpret_cast<float2*>(orow + (size_t)h * NQ * NO) = make_float2(lgA, lgB);
            }
        }
    }
}

// ---------------- softmax + weighted mean/var ----------------
__global__ void __launch_bounds__(256) k_attn() {
    __shared__ float w_s[16][NO];    // 32 KB
    const int bid = blockIdx.x;
    const int qt = bid & 31, h = (bid >> 5) & 7, b = bid >> 8;
    const int q0 = qt * 16;
    const int tid = threadIdx.x, lane = tid & 31, warp = tid >> 5;

    const float* lbase = g_logits + (size_t)(b * NH + h) * NQ * NO;
    for (int r = warp; r < 16; r += 8) {
        const float* lp = lbase + (size_t)(q0 + r) * NO;
        float vals[16];
        float mx = -3.0e38f;
#pragma unroll
        for (int j = 0; j < 16; j++) {
            vals[j] = lp[lane + j * 32];
            mx = fmaxf(mx, vals[j]);
        }
#pragma unroll
        for (int s = 16; s > 0; s >>= 1) mx = fmaxf(mx, __shfl_xor_sync(0xffffffffu, mx, s));
        float sum = 0.f;
#pragma unroll
        for (int j = 0; j < 16; j++) { vals[j] = expf(vals[j] - mx); sum += vals[j]; }
#pragma unroll
        for (int s = 16; s > 0; s >>= 1) sum += __shfl_xor_sync(0xffffffffu, sum, s);
        float inv = 1.f / sum;
#pragma unroll
        for (int j = 0; j < 16; j++) w_s[r][lane + j * 32] = vals[j] * inv;
    }
    __syncthreads();

    const int d = tid & 31, qq = tid >> 5;
    const float* vp = g_v + (size_t)(b * NO) * NHD + h * ND + d;
    float m1 = 0.f, e1 = 0.f, m2 = 0.f, e2 = 0.f;
#pragma unroll 4
    for (int o = 0; o < NO; o++) {
        float v  = __ldg(vp + (size_t)o * NHD);
        float v2 = v * v;
        float wa = w_s[qq][o];
        float wb = w_s[qq + 8][o];
        m1 = fmaf(wa, v, m1);  e1 = fmaf(wa, v2, e1);
        m2 = fmaf(wb, v, m2);  e2 = fmaf(wb, v2, e2);
    }
    size_t base = (size_t)(b * NQ + q0) * NHD + h * ND + d;
    g_hq [base + (size_t)qq * NHD]       = m1;
    g_var[base + (size_t)qq * NHD]       = e1 - m1 * m1;
    g_hq [base + (size_t)(qq + 8) * NHD] = m2;
    g_var[base + (size_t)(qq + 8) * NHD] = e2 - m2 * m2;
}

// ---------------- launcher ----------------
extern "C" void kernel_launch(void* const* d_in, const int* in_sizes, int n_in,
                              void* d_out, int out_size) {
    const float* h_obs     = (const float*)d_in[0];
    const float* pos_obs   = (const float*)d_in[1];
    const float* pos_query = (const float*)d_in[2];
    const float* fw1       = (const float*)d_in[3];
    const float* fb1       = (const float*)d_in[4];
    const float* fw2       = (const float*)d_in[5];
    const float* fb2       = (const float*)d_in[6];
    const float* log_sigma = (const float*)d_in[7];
    const float* kw1       = (const float*)d_in[8];
    const float* kb1       = (const float*)d_in[9];
    const float* kw2       = (const float*)d_in[10];
    const float* kb2       = (const float*)d_in[11];
    const float* ow        = (const float*)d_in[12];
    const float* ob        = (const float*)d_in[13];
    const float* vw        = (const float*)d_in[14];
    const float* vb        = (const float*)d_in[15];
    float* out = (float*)d_out;

    float *p_h1, *p_v, *p_hq, *p_var;
    cudaGetSymbolAddress((void**)&p_h1,  g_h1);
    cudaGetSymbolAddress((void**)&p_v,   g_v);
    cudaGetSymbolAddress((void**)&p_hq,  g_hq);
    cudaGetSymbolAddress((void**)&p_var, g_var);

    // position projections for the factored key-MLP
    k_posproj<<<NB * (NQ + NO), NL>>>(pos_obs, pos_query, kw1, kb1);

    // value MLP: v = relu(h_obs@fw1+fb1)@fw2+fb2  (ROWS=4 -> 256 blocks, better fill)
    k_gemm<256, 4, 1><<<NB * NO / 4, 256>>>(h_obs, fw1, fb1, p_h1);
    k_gemm<256, 4, 0><<<NB * NO / 4, 256>>>(p_h1, fw2, fb2, p_v);

    // logits = log(rbf+1e-8) + delta
    dim3 glog(NO / 32, NQ / 32, NB);
    k_logits<<<glog, 256>>>(pos_obs, pos_query, kw2, kb2, log_sigma);

    // softmax + weighted mean / variance
    k_attn<<<NB * NH * (NQ / 16), 256>>>();

    // fused output heads
    dim3 gout(NB * NQ / 8, 2);
    k_out<<<gout, NOUT>>>(p_hq, p_var, ow, ob, vw, vb, out);
}

// round 11
// speedup vs baseline: 1.4279x; 1.0377x over previous
#include <cuda_runtime.h>
#include <math.h>

#define NB   2
#define NO   512
#define NQ   512
#define NL   256
#define NH   8
#define ND   32
#define NHD  256
#define NOUT 128
#define KC   64
#define WP   (NO + 4)   // padded pitch for k_attn weight tile (kills bank conflicts)

typedef unsigned long long u64;

__device__ __forceinline__ u64 pack_dup(float x) {
    u64 r; asm("mov.b64 %0, {%1, %1};" : "=l"(r) : "f"(x)); return r;
}
__device__ __forceinline__ u64 pack2(float x, float y) {
    u64 r; asm("mov.b64 %0, {%1, %2};" : "=l"(r) : "f"(x), "f"(y)); return r;
}
__device__ __forceinline__ void fma2(u64 &d, u64 a, u64 b) {
    asm("fma.rn.f32x2 %0, %1, %2, %0;" : "+l"(d) : "l"(a), "l"(b));
}
__device__ __forceinline__ u64 mul2(u64 a, u64 b) {
    u64 r; asm("mul.rn.f32x2 %0, %1, %2;" : "=l"(r) : "l"(a), "l"(b)); return r;
}
__device__ __forceinline__ float2 unpack2(u64 v) {
    float2 r; asm("mov.b64 {%0, %1}, %2;" : "=f"(r.x), "=f"(r.y) : "l"(v)); return r;
}

// ---------------- scratch (device globals; no allocation allowed) ----------------
__device__ float g_aq[NB * NQ * NL];          // A_q + kb1
__device__ float g_ao[NB * NO * NL];          // A_o
__device__ float g_v [NB * NO * NHD];         // value features [b][o][h*32+d]
__device__ float g_logits[NB * NH * NQ * NO]; // [b][h][q][o]
__device__ float g_hq [NB * NQ * NHD];        // v_mean  [b][q][h*32+d]
__device__ float g_var[NB * NQ * NHD];        // variance [b][q][h*32+d]

// ---------------- position projections ----------------
__global__ void __launch_bounds__(NL) k_posproj(const float* __restrict__ pos_obs,
                                                const float* __restrict__ pos_query,
                                                const float* __restrict__ kw1,
                                                const float* __restrict__ kb1) {
    int row = blockIdx.x;
    int c   = threadIdx.x;
    if (row < NB * NQ) {
        const float* p = pos_query + row * 3;
        float acc = kb1[c];
#pragma unroll
        for (int i = 0; i < 3; i++)
            acc = fmaf(p[i], kw1[i * NL + c] + kw1[(6 + i) * NL + c], acc);
        g_aq[row * NL + c] = acc;
    } else {
        int r = row - NB * NQ;
        const float* p = pos_obs + r * 3;
        float acc = 0.f;
#pragma unroll
        for (int i = 0; i < 3; i++)
            acc = fmaf(p[i], kw1[(3 + i) * NL + c] - kw1[(6 + i) * NL + c], acc);
        g_ao[r * NL + c] = acc;
    }
}

// ---------------- fused value MLP: v = relu(h_obs@fw1+fb1)@fw2+fb2 ----------------
// 4 rows per CTA, 256 threads; intermediate h1 lives in smem only.
__global__ void __launch_bounds__(256) k_vmlp(const float* __restrict__ A,
                                              const float* __restrict__ fw1,
                                              const float* __restrict__ fb1,
                                              const float* __restrict__ fw2,
                                              const float* __restrict__ fb2,
                                              float* __restrict__ V) {
    __shared__ __align__(16) float a_s[4][NL];
    __shared__ __align__(16) float h_s[4][NL];
    const int tid  = threadIdx.x;
    const int row0 = blockIdx.x * 4;

    for (int idx = tid; idx < 4 * NL; idx += 256)
        a_s[idx >> 8][idx & 255] = A[(row0 + (idx >> 8)) * NL + (idx & 255)];
    __syncthreads();

    float acc[4];
#pragma unroll
    for (int r = 0; r < 4; r++) acc[r] = 0.f;
    for (int k4 = 0; k4 < NL; k4 += 4) {
        float w0 = fw1[(k4 + 0) * NL + tid];
        float w1 = fw1[(k4 + 1) * NL + tid];
        float w2 = fw1[(k4 + 2) * NL + tid];
        float w3 = fw1[(k4 + 3) * NL + tid];
#pragma unroll
        for (int r = 0; r < 4; r++) {
            float4 a = *reinterpret_cast<const float4*>(&a_s[r][k4]);
            acc[r] = fmaf(a.x, w0, acc[r]);
            acc[r] = fmaf(a.y, w1, acc[r]);
            acc[r] = fmaf(a.z, w2, acc[r]);
            acc[r] = fmaf(a.w, w3, acc[r]);
        }
    }
    float b1 = fb1[tid];
#pragma unroll
    for (int r = 0; r < 4; r++) h_s[r][tid] = fmaxf(acc[r] + b1, 0.f);
    __syncthreads();

#pragma unroll
    for (int r = 0; r < 4; r++) acc[r] = 0.f;
    for (int k4 = 0; k4 < NL; k4 += 4) {
        float w0 = fw2[(k4 + 0) * NHD + tid];
        float w1 = fw2[(k4 + 1) * NHD + tid];
        float w2 = fw2[(k4 + 2) * NHD + tid];
        float w3 = fw2[(k4 + 3) * NHD + tid];
#pragma unroll
        for (int r = 0; r < 4; r++) {
            float4 a = *reinterpret_cast<const float4*>(&h_s[r][k4]);
            acc[r] = fmaf(a.x, w0, acc[r]);
            acc[r] = fmaf(a.y, w1, acc[r]);
            acc[r] = fmaf(a.z, w2, acc[r]);
            acc[r] = fmaf(a.w, w3, acc[r]);
        }
    }
    float b2 = fb2[tid];
#pragma unroll
    for (int r = 0; r < 4; r++) V[(row0 + r) * NHD + tid] = acc[r] + b2;
}

// ---------------- fused output heads ----------------
__global__ void __launch_bounds__(NOUT) k_out(const float* __restrict__ hq,
                                              const float* __restrict__ var,
                                              const float* __restrict__ ow,
                                              const float* __restrict__ ob,
                                              const float* __restrict__ vw,
                                              const float* __restrict__ vb,
                                              float* __restrict__ out) {
    __shared__ __align__(16) float a_s[8][NL];
    const int tid  = threadIdx.x;
    const int row0 = blockIdx.x * 8;
    const int sel  = blockIdx.y;
    const float* A    = sel ? var : hq;
    const float* W    = sel ? vw  : ow;
    const float* bias = sel ? vb  : ob;
    float* C = out + (sel ? (size_t)NB * NQ * NOUT : 0);

    for (int idx = tid; idx < 8 * NL; idx += NOUT)
        a_s[idx >> 8][idx & 255] = A[(row0 + (idx >> 8)) * NL + (idx & 255)];
    __syncthreads();

    float acc[8];
#pragma unroll
    for (int r = 0; r < 8; r++) acc[r] = 0.f;

    for (int k4 = 0; k4 < NL; k4 += 4) {
        float w0 = W[(k4 + 0) * NOUT + tid];
        float w1 = W[(k4 + 1) * NOUT + tid];
        float w2 = W[(k4 + 2) * NOUT + tid];
        float w3 = W[(k4 + 3) * NOUT + tid];
#pragma unroll
        for (int r = 0; r < 8; r++) {
            float4 a = *reinterpret_cast<const float4*>(&a_s[r][k4]);
            acc[r] = fmaf(a.x, w0, acc[r]);
            acc[r] = fmaf(a.y, w1, acc[r]);
            acc[r] = fmaf(a.z, w2, acc[r]);
            acc[r] = fmaf(a.w, w3, acc[r]);
        }
    }
    float bb = bias[tid];
#pragma unroll
    for (int r = 0; r < 8; r++) {
        float v = acc[r] + bb;
        if (sel) v = fmaxf(v, 0.f) + log1pf(expf(-fabsf(v)));
        C[(row0 + r) * NOUT + tid] = v;
    }
}

// ---------------- logits: delta MLP + RBF, fused (2x2 reg tile + f32x2 heads) ----------------
// __launch_bounds__(256,4): cap regs at 64 so all 512 CTAs are co-resident (no tail wave).
__global__ void __launch_bounds__(256, 4) k_logits(const float* __restrict__ pos_obs,
                                                   const float* __restrict__ pos_query,
                                                   const float* __restrict__ kw2,
                                                   const float* __restrict__ kb2,
                                                   const float* __restrict__ log_sigma) {
    __shared__ __align__(16) float kw2_s[NL * NH];   // 8 KB
    __shared__ float aq_s[KC * 34];
    __shared__ float ao_s[KC * 34];
    __shared__ float pq_s[32][3], po_s[32][3];
    __shared__ float inv_s2[NH], kb2_s[NH];

    const int tid = threadIdx.x;
    const int o0  = blockIdx.x * 32;
    const int q0  = blockIdx.y * 32;
    const int b   = blockIdx.z;
    const int ol  = tid & 15;
    const int ql  = tid >> 4;

    for (int idx = tid; idx < NL * NH; idx += 256) kw2_s[idx] = kw2[idx];
    if (tid < 96) {
        pq_s[tid / 3][tid % 3] = pos_query[(b * NQ + q0) * 3 + tid];
    } else if (tid < 192) {
        int t = tid - 96;
        po_s[t / 3][t % 3] = pos_obs[(b * NO + o0) * 3 + t];
    } else if (tid < 200) {
        int h = tid - 192;
        float s   = expf(log_sigma[h]);
        inv_s2[h] = 1.f / (s * s + 1e-6f);
        kb2_s[h]  = kb2[h];
    }

    u64 acc[4][4];
#pragma unroll
    for (int p = 0; p < 4; p++)
#pragma unroll
        for (int j = 0; j < 4; j++) acc[p][j] = 0ULL;

    const float* aqg = g_aq + (size_t)(b * NQ + q0) * NL;
    const float* aog = g_ao + (size_t)(b * NO + o0) * NL;

    for (int kc = 0; kc < NL; kc += KC) {
        __syncthreads();
        for (int idx = tid; idx < (KC / 2) * 32; idx += 256) {
            int kk2 = (idx & 31) * 2, rr = idx >> 5;
            float2 va = *reinterpret_cast<const float2*>(aqg + rr * NL + kc + kk2);
            aq_s[kk2 * 34 + rr]       = va.x;
            aq_s[(kk2 + 1) * 34 + rr] = va.y;
            float2 vo = *reinterpret_cast<const float2*>(aog + rr * NL + kc + kk2);
            ao_s[kk2 * 34 + rr]       = vo.x;
            ao_s[(kk2 + 1) * 34 + rr] = vo.y;
        }
        __syncthreads();

#pragma unroll 4
        for (int kk = 0; kk < KC; kk++) {
            float2 aq2 = *reinterpret_cast<const float2*>(&aq_s[kk * 34 + 2 * ql]);
            float2 ao2 = *reinterpret_cast<const float2*>(&ao_s[kk * 34 + 2 * ol]);
            float h00 = fmaxf(aq2.x + ao2.x, 0.f);
            float h01 = fmaxf(aq2.x + ao2.y, 0.f);
            float h10 = fmaxf(aq2.y + ao2.x, 0.f);
            float h11 = fmaxf(aq2.y + ao2.y, 0.f);
            u64 d00 = pack_dup(h00), d01 = pack_dup(h01);
            u64 d10 = pack_dup(h10), d11 = pack_dup(h11);
            const ulonglong2* wp = reinterpret_cast<const ulonglong2*>(kw2_s + (kc + kk) * 8);
            ulonglong2 wA = wp[0], wB = wp[1];
            fma2(acc[0][0], d00, wA.x); fma2(acc[0][1], d00, wA.y);
            fma2(acc[0][2], d00, wB.x); fma2(acc[0][3], d00, wB.y);
            fma2(acc[1][0], d01, wA.x); fma2(acc[1][1], d01, wA.y);
            fma2(acc[1][2], d01, wB.x); fma2(acc[1][3], d01, wB.y);
            fma2(acc[2][0], d10, wA.x); fma2(acc[2][1], d10, wA.y);
            fma2(acc[2][2], d10, wB.x); fma2(acc[2][3], d10, wB.y);
            fma2(acc[3][0], d11, wA.x); fma2(acc[3][1], d11, wA.y);
            fma2(acc[3][2], d11, wB.x); fma2(acc[3][3], d11, wB.y);
        }
    }

    const int oA = o0 + 2 * ol;
    const float pax = po_s[2 * ol][0],     pay = po_s[2 * ol][1],     paz = po_s[2 * ol][2];
    const float pbx = po_s[2 * ol + 1][0], pby = po_s[2 * ol + 1][1], pbz = po_s[2 * ol + 1][2];

#pragma unroll
    for (int qi = 0; qi < 2; qi++) {
        int q = q0 + 2 * ql + qi;
        float px = pq_s[2 * ql + qi][0], py = pq_s[2 * ql + qi][1], pz = pq_s[2 * ql + qi][2];
        float dxA = px - pax, dyA = py - pay, dzA = pz - paz;
        float dxB = px - pbx, dyB = py - pby, dzB = pz - pbz;
        float d2A = dxA * dxA + dyA * dyA + dzA * dzA;
        float d2B = dxB * dxB + dyB * dyB + dzB * dzB;
        float* orow = g_logits + ((size_t)(b * NH) * NQ + q) * NO + oA;
#pragma unroll
        for (int hp = 0; hp < 4; hp++) {
            float2 vA = unpack2(acc[qi * 2 + 0][hp]);
            float2 vB = unpack2(acc[qi * 2 + 1][hp]);
#pragma unroll
            for (int hl = 0; hl < 2; hl++) {
                int h = 2 * hp + hl;
                float va  = hl ? vA.y : vA.x;
                float vbb = hl ? vB.y : vB.x;
                float lgA = logf(expf(-d2A * inv_s2[h]) + 1e-8f) + va  + kb2_s[h];
                float lgB = logf(expf(-d2B * inv_s2[h]) + 1e-8f) + vbb + kb2_s[h];
                *reinterpret_cast<float2*>(orow + (size_t)h * NQ * NO) = make_float2(lgA, lgB);
            }
        }
    }
}

// ---------------- softmax + weighted mean/var (f32x2 over d-pairs) ----------------
__global__ void __launch_bounds__(256) k_attn() {
    __shared__ float w_s[16][WP];    // padded pitch: conflict-free row access
    const int bid = blockIdx.x;
    const int qt = bid & 31, h = (bid >> 5) & 7, b = bid >> 8;
    const int q0 = qt * 16;
    const int tid = threadIdx.x, lane = tid & 31, warp = tid >> 5;

    const float* lbase = g_logits + (size_t)(b * NH + h) * NQ * NO;
    for (int r = warp; r < 16; r += 8) {
        const float* lp = lbase + (size_t)(q0 + r) * NO;
        float vals[16];
        float mx = -3.0e38f;
#pragma unroll
        for (int j = 0; j < 16; j++) {
            vals[j] = lp[lane + j * 32];
            mx = fmaxf(mx, vals[j]);
        }
#pragma unroll
        for (int s = 16; s > 0; s >>= 1) mx = fmaxf(mx, __shfl_xor_sync(0xffffffffu, mx, s));
        float sum = 0.f;
#pragma unroll
        for (int j = 0; j < 16; j++) { vals[j] = expf(vals[j] - mx); sum += vals[j]; }
#pragma unroll
        for (int s = 16; s > 0; s >>= 1) sum += __shfl_xor_sync(0xffffffffu, sum, s);
        float inv = 1.f / sum;
#pragma unroll
        for (int j = 0; j < 16; j++) w_s[r][lane + j * 32] = vals[j] * inv;
    }
    __syncthreads();

    // phase 2: thread = (row r, d-pair dp). mean/E2 accumulated as packed f32x2.
    const int dp = tid & 15;     // d = 2*dp, 2*dp+1
    const int r  = tid >> 4;     // row 0..15
    const float* vp = g_v + (size_t)(b * NO) * NHD + h * ND + 2 * dp;
    u64 m = 0ULL, e = 0ULL;
#pragma unroll 4
    for (int o = 0; o < NO; o++) {
        float2 v2 = *reinterpret_cast<const float2*>(vp + (size_t)o * NHD);
        u64 vv = pack2(v2.x, v2.y);
        u64 sq = mul2(vv, vv);
        u64 wd = pack_dup(w_s[r][o]);
        fma2(m, vv, wd);
        fma2(e, sq, wd);
    }
    float2 mm = unpack2(m), ee = unpack2(e);
    size_t base = (size_t)(b * NQ + q0 + r) * NHD + h * ND + 2 * dp;
    *reinterpret_cast<float2*>(g_hq  + base) = mm;
    *reinterpret_cast<float2*>(g_var + base) =
        make_float2(ee.x - mm.x * mm.x, ee.y - mm.y * mm.y);
}

// ---------------- launcher ----------------
extern "C" void kernel_launch(void* const* d_in, const int* in_sizes, int n_in,
                              void* d_out, int out_size) {
    const float* h_obs     = (const float*)d_in[0];
    const float* pos_obs   = (const float*)d_in[1];
    const float* pos_query = (const float*)d_in[2];
    const float* fw1       = (const float*)d_in[3];
    const float* fb1       = (const float*)d_in[4];
    const float* fw2       = (const float*)d_in[5];
    const float* fb2       = (const float*)d_in[6];
    const float* log_sigma = (const float*)d_in[7];
    const float* kw1       = (const float*)d_in[8];
    const float* kb1       = (const float*)d_in[9];
    const float* kw2       = (const float*)d_in[10];
    const float* kb2       = (const float*)d_in[11];
    const float* ow        = (const float*)d_in[12];
    const float* ob        = (const float*)d_in[13];
    const float* vw        = (const float*)d_in[14];
    const float* vb        = (const float*)d_in[15];
    float* out = (float*)d_out;

    float *p_v, *p_hq, *p_var;
    cudaGetSymbolAddress((void**)&p_v,   g_v);
    cudaGetSymbolAddress((void**)&p_hq,  g_hq);
    cudaGetSymbolAddress((void**)&p_var, g_var);

    // position projections for the factored key-MLP
    k_posproj<<<NB * (NQ + NO), NL>>>(pos_obs, pos_query, kw1, kb1);

    // fused value MLP
    k_vmlp<<<NB * NO / 4, 256>>>(h_obs, fw1, fb1, fw2, fb2, p_v);

    // logits = log(rbf+1e-8) + delta
    dim3 glog(NO / 32, NQ / 32, NB);
    k_logits<<<glog, 256>>>(pos_obs, pos_query, kw2, kb2, log_sigma);

    // softmax + weighted mean / variance
    k_attn<<<NB * NH * (NQ / 16), 256>>>();

    // fused output heads
    dim3 gout(NB * NQ / 8, 2);
    k_out<<<gout, NOUT>>>(p_hq, p_var, ow, ob, vw, vb, out);
}

// round 12
// speedup vs baseline: 1.4299x; 1.0014x over previous
#include <cuda_runtime.h>
#include <math.h>

#define NB   2
#define NO   512
#define NQ   512
#define NL   256
#define NH   8
#define ND   32
#define NHD  256
#define NOUT 128
#define KC   64
#define WP   (NO + 4)   // padded pitch for k_attn weight tile (kills bank conflicts)

typedef unsigned long long u64;

__device__ __forceinline__ u64 pack_dup(float x) {
    u64 r; asm("mov.b64 %0, {%1, %1};" : "=l"(r) : "f"(x)); return r;
}
__device__ __forceinline__ u64 pack2(float x, float y) {
    u64 r; asm("mov.b64 %0, {%1, %2};" : "=l"(r) : "f"(x), "f"(y)); return r;
}
__device__ __forceinline__ void fma2(u64 &d, u64 a, u64 b) {
    asm("fma.rn.f32x2 %0, %1, %2, %0;" : "+l"(d) : "l"(a), "l"(b));
}
__device__ __forceinline__ u64 mul2(u64 a, u64 b) {
    u64 r; asm("mul.rn.f32x2 %0, %1, %2;" : "=l"(r) : "l"(a), "l"(b)); return r;
}
__device__ __forceinline__ float2 unpack2(u64 v) {
    float2 r; asm("mov.b64 {%0, %1}, %2;" : "=f"(r.x), "=f"(r.y) : "l"(v)); return r;
}

// ---------------- scratch (device globals; no allocation allowed) ----------------
__device__ float g_aq[NB * NQ * NL];          // A_q + kb1
__device__ float g_ao[NB * NO * NL];          // A_o
__device__ float g_v [NB * NO * NHD];         // value features [b][o][h*32+d]
__device__ float g_logits[NB * NH * NQ * NO]; // [b][h][q][o]
__device__ float g_hq [NB * NQ * NHD];        // v_mean  [b][q][h*32+d]
__device__ float g_var[NB * NQ * NHD];        // variance [b][q][h*32+d]

// ---------------- position projections ----------------
__global__ void __launch_bounds__(NL) k_posproj(const float* __restrict__ pos_obs,
                                                const float* __restrict__ pos_query,
                                                const float* __restrict__ kw1,
                                                const float* __restrict__ kb1) {
    int row = blockIdx.x;
    int c   = threadIdx.x;
    if (row < NB * NQ) {
        const float* p = pos_query + row * 3;
        float acc = kb1[c];
#pragma unroll
        for (int i = 0; i < 3; i++)
            acc = fmaf(p[i], kw1[i * NL + c] + kw1[(6 + i) * NL + c], acc);
        g_aq[row * NL + c] = acc;
    } else {
        int r = row - NB * NQ;
        const float* p = pos_obs + r * 3;
        float acc = 0.f;
#pragma unroll
        for (int i = 0; i < 3; i++)
            acc = fmaf(p[i], kw1[(3 + i) * NL + c] - kw1[(6 + i) * NL + c], acc);
        g_ao[r * NL + c] = acc;
    }
}

// ---------------- fused value MLP: v = relu(h_obs@fw1+fb1)@fw2+fb2 ----------------
// 4 rows per CTA, 256 threads; intermediate h1 lives in smem only.
__global__ void __launch_bounds__(256) k_vmlp(const float* __restrict__ A,
                                              const float* __restrict__ fw1,
                                              const float* __restrict__ fb1,
                                              const float* __restrict__ fw2,
                                              const float* __restrict__ fb2,
                                              float* __restrict__ V) {
    __shared__ __align__(16) float a_s[4][NL];
    __shared__ __align__(16) float h_s[4][NL];
    const int tid  = threadIdx.x;
    const int row0 = blockIdx.x * 4;

    for (int idx = tid; idx < 4 * NL; idx += 256)
        a_s[idx >> 8][idx & 255] = A[(row0 + (idx >> 8)) * NL + (idx & 255)];
    __syncthreads();

    float acc[4];
#pragma unroll
    for (int r = 0; r < 4; r++) acc[r] = 0.f;
    for (int k4 = 0; k4 < NL; k4 += 4) {
        float w0 = fw1[(k4 + 0) * NL + tid];
        float w1 = fw1[(k4 + 1) * NL + tid];
        float w2 = fw1[(k4 + 2) * NL + tid];
        float w3 = fw1[(k4 + 3) * NL + tid];
#pragma unroll
        for (int r = 0; r < 4; r++) {
            float4 a = *reinterpret_cast<const float4*>(&a_s[r][k4]);
            acc[r] = fmaf(a.x, w0, acc[r]);
            acc[r] = fmaf(a.y, w1, acc[r]);
            acc[r] = fmaf(a.z, w2, acc[r]);
            acc[r] = fmaf(a.w, w3, acc[r]);
        }
    }
    float b1 = fb1[tid];
#pragma unroll
    for (int r = 0; r < 4; r++) h_s[r][tid] = fmaxf(acc[r] + b1, 0.f);
    __syncthreads();

#pragma unroll
    for (int r = 0; r < 4; r++) acc[r] = 0.f;
    for (int k4 = 0; k4 < NL; k4 += 4) {
        float w0 = fw2[(k4 + 0) * NHD + tid];
        float w1 = fw2[(k4 + 1) * NHD + tid];
        float w2 = fw2[(k4 + 2) * NHD + tid];
        float w3 = fw2[(k4 + 3) * NHD + tid];
#pragma unroll
        for (int r = 0; r < 4; r++) {
            float4 a = *reinterpret_cast<const float4*>(&h_s[r][k4]);
            acc[r] = fmaf(a.x, w0, acc[r]);
            acc[r] = fmaf(a.y, w1, acc[r]);
            acc[r] = fmaf(a.z, w2, acc[r]);
            acc[r] = fmaf(a.w, w3, acc[r]);
        }
    }
    float b2 = fb2[tid];
#pragma unroll
    for (int r = 0; r < 4; r++) V[(row0 + r) * NHD + tid] = acc[r] + b2;
}

// ---------------- fused output heads ----------------
__global__ void __launch_bounds__(NOUT) k_out(const float* __restrict__ hq,
                                              const float* __restrict__ var,
                                              const float* __restrict__ ow,
                                              const float* __restrict__ ob,
                                              const float* __restrict__ vw,
                                              const float* __restrict__ vb,
                                              float* __restrict__ out) {
    __shared__ __align__(16) float a_s[8][NL];
    const int tid  = threadIdx.x;
    const int row0 = blockIdx.x * 8;
    const int sel  = blockIdx.y;
    const float* A    = sel ? var : hq;
    const float* W    = sel ? vw  : ow;
    const float* bias = sel ? vb  : ob;
    float* C = out + (sel ? (size_t)NB * NQ * NOUT : 0);

    for (int idx = tid; idx < 8 * NL; idx += NOUT)
        a_s[idx >> 8][idx & 255] = A[(row0 + (idx >> 8)) * NL + (idx & 255)];
    __syncthreads();

    float acc[8];
#pragma unroll
    for (int r = 0; r < 8; r++) acc[r] = 0.f;

    for (int k4 = 0; k4 < NL; k4 += 4) {
        float w0 = W[(k4 + 0) * NOUT + tid];
        float w1 = W[(k4 + 1) * NOUT + tid];
        float w2 = W[(k4 + 2) * NOUT + tid];
        float w3 = W[(k4 + 3) * NOUT + tid];
#pragma unroll
        for (int r = 0; r < 8; r++) {
            float4 a = *reinterpret_cast<const float4*>(&a_s[r][k4]);
            acc[r] = fmaf(a.x, w0, acc[r]);
            acc[r] = fmaf(a.y, w1, acc[r]);
            acc[r] = fmaf(a.z, w2, acc[r]);
            acc[r] = fmaf(a.w, w3, acc[r]);
        }
    }
    float bb = bias[tid];
#pragma unroll
    for (int r = 0; r < 8; r++) {
        float v = acc[r] + bb;
        if (sel) v = fmaxf(v, 0.f) + log1pf(expf(-fabsf(v)));
        C[(row0 + r) * NOUT + tid] = v;
    }
}

// ---------------- logits: delta MLP + RBF, fused (2x2 reg tile + f32x2 heads) ----------------
// __launch_bounds__(256,4): cap regs at 64 so all 512 CTAs are co-resident (no tail wave).
__global__ void __launch_bounds__(256, 4) k_logits(const float* __restrict__ pos_obs,
                                                   const float* __restrict__ pos_query,
                                                   const float* __restrict__ kw2,
                                                   const float* __restrict__ kb2,
                                                   const float* __restrict__ log_sigma) {
    __shared__ __align__(16) float kw2_s[NL * NH];   // 8 KB
    __shared__ float aq_s[KC * 34];
    __shared__ float ao_s[KC * 34];
    __shared__ float pq_s[32][3], po_s[32][3];
    __shared__ float inv_s2[NH], kb2_s[NH];

    const int tid = threadIdx.x;
    const int o0  = blockIdx.x * 32;
    const int q0  = blockIdx.y * 32;
    const int b   = blockIdx.z;
    const int ol  = tid & 15;
    const int ql  = tid >> 4;

    for (int idx = tid; idx < NL * NH; idx += 256) kw2_s[idx] = kw2[idx];
    if (tid < 96) {
        pq_s[tid / 3][tid % 3] = pos_query[(b * NQ + q0) * 3 + tid];
    } else if (tid < 192) {
        int t = tid - 96;
        po_s[t / 3][t % 3] = pos_obs[(b * NO + o0) * 3 + t];
    } else if (tid < 200) {
        int h = tid - 192;
        float s   = expf(log_sigma[h]);
        inv_s2[h] = 1.f / (s * s + 1e-6f);
        kb2_s[h]  = kb2[h];
    }

    u64 acc[4][4];
#pragma unroll
    for (int p = 0; p < 4; p++)
#pragma unroll
        for (int j = 0; j < 4; j++) acc[p][j] = 0ULL;

    const float* aqg = g_aq + (size_t)(b * NQ + q0) * NL;
    const float* aog = g_ao + (size_t)(b * NO + o0) * NL;

    for (int kc = 0; kc < NL; kc += KC) {
        __syncthreads();
        for (int idx = tid; idx < (KC / 2) * 32; idx += 256) {
            int kk2 = (idx & 31) * 2, rr = idx >> 5;
            float2 va = *reinterpret_cast<const float2*>(aqg + rr * NL + kc + kk2);
            aq_s[kk2 * 34 + rr]       = va.x;
            aq_s[(kk2 + 1) * 34 + rr] = va.y;
            float2 vo = *reinterpret_cast<const float2*>(aog + rr * NL + kc + kk2);
            ao_s[kk2 * 34 + rr]       = vo.x;
            ao_s[(kk2 + 1) * 34 + rr] = vo.y;
        }
        __syncthreads();

#pragma unroll 4
        for (int kk = 0; kk < KC; kk++) {
            float2 aq2 = *reinterpret_cast<const float2*>(&aq_s[kk * 34 + 2 * ql]);
            float2 ao2 = *reinterpret_cast<const float2*>(&ao_s[kk * 34 + 2 * ol]);
            float h00 = fmaxf(aq2.x + ao2.x, 0.f);
            float h01 = fmaxf(aq2.x + ao2.y, 0.f);
            float h10 = fmaxf(aq2.y + ao2.x, 0.f);
            float h11 = fmaxf(aq2.y + ao2.y, 0.f);
            u64 d00 = pack_dup(h00), d01 = pack_dup(h01);
            u64 d10 = pack_dup(h10), d11 = pack_dup(h11);
            const ulonglong2* wp = reinterpret_cast<const ulonglong2*>(kw2_s + (kc + kk) * 8);
            ulonglong2 wA = wp[0], wB = wp[1];
            fma2(acc[0][0], d00, wA.x); fma2(acc[0][1], d00, wA.y);
            fma2(acc[0][2], d00, wB.x); fma2(acc[0][3], d00, wB.y);
            fma2(acc[1][0], d01, wA.x); fma2(acc[1][1], d01, wA.y);
            fma2(acc[1][2], d01, wB.x); fma2(acc[1][3], d01, wB.y);
            fma2(acc[2][0], d10, wA.x); fma2(acc[2][1], d10, wA.y);
            fma2(acc[2][2], d10, wB.x); fma2(acc[2][3], d10, wB.y);
            fma2(acc[3][0], d11, wA.x); fma2(acc[3][1], d11, wA.y);
            fma2(acc[3][2], d11, wB.x); fma2(acc[3][3], d11, wB.y);
        }
    }

    const int oA = o0 + 2 * ol;
    const float pax = po_s[2 * ol][0],     pay = po_s[2 * ol][1],     paz = po_s[2 * ol][2];
    const float pbx = po_s[2 * ol + 1][0], pby = po_s[2 * ol + 1][1], pbz = po_s[2 * ol + 1][2];

#pragma unroll
    for (int qi = 0; qi < 2; qi++) {
        int q = q0 + 2 * ql + qi;
        float px = pq_s[2 * ql + qi][0], py = pq_s[2 * ql + qi][1], pz = pq_s[2 * ql + qi][2];
        float dxA = px - pax, dyA = py - pay, dzA = pz - paz;
        float dxB = px - pbx, dyB = py - pby, dzB = pz - pbz;
        float d2A = dxA * dxA + dyA * dyA + dzA * dzA;
        float d2B = dxB * dxB + dyB * dyB + dzB * dzB;
        float* orow = g_logits + ((size_t)(b * NH) * NQ + q) * NO + oA;
#pragma unroll
        for (int hp = 0; hp < 4; hp++) {
            float2 vA = unpack2(acc[qi * 2 + 0][hp]);
            float2 vB = unpack2(acc[qi * 2 + 1][hp]);
#pragma unroll
            for (int hl = 0; hl < 2; hl++) {
                int h = 2 * hp + hl;
                float va  = hl ? vA.y : vA.x;
                float vbb = hl ? vB.y : vB.x;
                float lgA = logf(expf(-d2A * inv_s2[h]) + 1e-8f) + va  + kb2_s[h];
                float lgB = logf(expf(-d2B * inv_s2[h]) + 1e-8f) + vbb + kb2_s[h];
                *reinterpret_cast<float2*>(orow + (size_t)h * NQ * NO) = make_float2(lgA, lgB);
            }
        }
    }
}

// ---------------- softmax + weighted mean/var (f32x2 over d-pairs) ----------------
__global__ void __launch_bounds__(256) k_attn() {
    __shared__ float w_s[16][WP];    // padded pitch: conflict-free row access
    const int bid = blockIdx.x;
    const int qt = bid & 31, h = (bid >> 5) & 7, b = bid >> 8;
    const int q0 = qt * 16;
    const int tid = threadIdx.x, lane = tid & 31, warp = tid >> 5;

    const float* lbase = g_logits + (size_t)(b * NH + h) * NQ * NO;
    for (int r = warp; r < 16; r += 8) {
        const float* lp = lbase + (size_t)(q0 + r) * NO;
        float vals[16];
        float mx = -3.0e38f;
#pragma unroll
        for (int j = 0; j < 16; j++) {
            vals[j] = lp[lane + j * 32];
            mx = fmaxf(mx, vals[j]);
        }
#pragma unroll
        for (int s = 16; s > 0; s >>= 1) mx = fmaxf(mx, __shfl_xor_sync(0xffffffffu, mx, s));
        float sum = 0.f;
#pragma unroll
        for (int j = 0; j < 16; j++) { vals[j] = expf(vals[j] - mx); sum += vals[j]; }
#pragma unroll
        for (int s = 16; s > 0; s >>= 1) sum += __shfl_xor_sync(0xffffffffu, sum, s);
        float inv = 1.f / sum;
#pragma unroll
        for (int j = 0; j < 16; j++) w_s[r][lane + j * 32] = vals[j] * inv;
    }
    __syncthreads();

    // phase 2: thread = (row r, d-pair dp). mean/E2 accumulated as packed f32x2.
    const int dp = tid & 15;     // d = 2*dp, 2*dp+1
    const int r  = tid >> 4;     // row 0..15
    const float* vp = g_v + (size_t)(b * NO) * NHD + h * ND + 2 * dp;
    u64 m = 0ULL, e = 0ULL;
#pragma unroll 4
    for (int o = 0; o < NO; o++) {
        float2 v2 = *reinterpret_cast<const float2*>(vp + (size_t)o * NHD);
        u64 vv = pack2(v2.x, v2.y);
        u64 sq = mul2(vv, vv);
        u64 wd = pack_dup(w_s[r][o]);
        fma2(m, vv, wd);
        fma2(e, sq, wd);
    }
    float2 mm = unpack2(m), ee = unpack2(e);
    size_t base = (size_t)(b * NQ + q0 + r) * NHD + h * ND + 2 * dp;
    *reinterpret_cast<float2*>(g_hq  + base) = mm;
    *reinterpret_cast<float2*>(g_var + base) =
        make_float2(ee.x - mm.x * mm.x, ee.y - mm.y * mm.y);
}

// ---------------- launcher ----------------
extern "C" void kernel_launch(void* const* d_in, const int* in_sizes, int n_in,
                              void* d_out, int out_size) {
    const float* h_obs     = (const float*)d_in[0];
    const float* pos_obs   = (const float*)d_in[1];
    const float* pos_query = (const float*)d_in[2];
    const float* fw1       = (const float*)d_in[3];
    const float* fb1       = (const float*)d_in[4];
    const float* fw2       = (const float*)d_in[5];
    const float* fb2       = (const float*)d_in[6];
    const float* log_sigma = (const float*)d_in[7];
    const float* kw1       = (const float*)d_in[8];
    const float* kb1       = (const float*)d_in[9];
    const float* kw2       = (const float*)d_in[10];
    const float* kb2       = (const float*)d_in[11];
    const float* ow        = (const float*)d_in[12];
    const float* ob        = (const float*)d_in[13];
    const float* vw        = (const float*)d_in[14];
    const float* vb        = (const float*)d_in[15];
    float* out = (float*)d_out;

    float *p_v, *p_hq, *p_var;
    cudaGetSymbolAddress((void**)&p_v,   g_v);
    cudaGetSymbolAddress((void**)&p_hq,  g_hq);
    cudaGetSymbolAddress((void**)&p_var, g_var);

    // position projections for the factored key-MLP
    k_posproj<<<NB * (NQ + NO), NL>>>(pos_obs, pos_query, kw1, kb1);

    // fused value MLP
    k_vmlp<<<NB * NO / 4, 256>>>(h_obs, fw1, fb1, fw2, fb2, p_v);

    // logits = log(rbf+1e-8) + delta
    dim3 glog(NO / 32, NQ / 32, NB);
    k_logits<<<glog, 256>>>(pos_obs, pos_query, kw2, kb2, log_sigma);

    // softmax + weighted mean / variance
    k_attn<<<NB * NH * (NQ / 16), 256>>>();

    // fused output heads
    dim3 gout(NB * NQ / 8, 2);
    k_out<<<gout, NOUT>>>(p_hq, p_var, ow, ob, vw, vb, out);
}

// round 13
// speedup vs baseline: 1.4302x; 1.0002x over previous
#include <cuda_runtime.h>
#include <math.h>

#define NB   2
#define NO   512
#define NQ   512
#define NL   256
#define NH   8
#define ND   32
#define NHD  256
#define NOUT 128
#define KC   64
#define WP   (NO + 4)   // padded pitch for k_attn weight tile (kills bank conflicts)

typedef unsigned long long u64;

__device__ __forceinline__ u64 pack_dup(float x) {
    u64 r; asm("mov.b64 %0, {%1, %1};" : "=l"(r) : "f"(x)); return r;
}
__device__ __forceinline__ u64 pack2(float x, float y) {
    u64 r; asm("mov.b64 %0, {%1, %2};" : "=l"(r) : "f"(x), "f"(y)); return r;
}
__device__ __forceinline__ void fma2(u64 &d, u64 a, u64 b) {
    asm("fma.rn.f32x2 %0, %1, %2, %0;" : "+l"(d) : "l"(a), "l"(b));
}
__device__ __forceinline__ u64 mul2(u64 a, u64 b) {
    u64 r; asm("mul.rn.f32x2 %0, %1, %2;" : "=l"(r) : "l"(a), "l"(b)); return r;
}
__device__ __forceinline__ float2 unpack2(u64 v) {
    float2 r; asm("mov.b64 {%0, %1}, %2;" : "=f"(r.x), "=f"(r.y) : "l"(v)); return r;
}

// ---------------- scratch (device globals; no allocation allowed) ----------------
__device__ float g_aq[NB * NQ * NL];          // A_q + kb1
__device__ float g_ao[NB * NO * NL];          // A_o
__device__ float g_v [NB * NO * NHD];         // value features [b][o][h*32+d]
__device__ float g_logits[NB * NH * NQ * NO]; // [b][h][q][o]
__device__ float g_hq [NB * NQ * NHD];        // v_mean  [b][q][h*32+d]
__device__ float g_var[NB * NQ * NHD];        // variance [b][q][h*32+d]

// ---------------- position projections ----------------
__global__ void __launch_bounds__(NL) k_posproj(const float* __restrict__ pos_obs,
                                                const float* __restrict__ pos_query,
                                                const float* __restrict__ kw1,
                                                const float* __restrict__ kb1) {
    int row = blockIdx.x;
    int c   = threadIdx.x;
    if (row < NB * NQ) {
        const float* p = pos_query + row * 3;
        float acc = kb1[c];
#pragma unroll
        for (int i = 0; i < 3; i++)
            acc = fmaf(p[i], kw1[i * NL + c] + kw1[(6 + i) * NL + c], acc);
        g_aq[row * NL + c] = acc;
    } else {
        int r = row - NB * NQ;
        const float* p = pos_obs + r * 3;
        float acc = 0.f;
#pragma unroll
        for (int i = 0; i < 3; i++)
            acc = fmaf(p[i], kw1[(3 + i) * NL + c] - kw1[(6 + i) * NL + c], acc);
        g_ao[r * NL + c] = acc;
    }
}

// ---------------- fused value MLP: v = relu(h_obs@fw1+fb1)@fw2+fb2 ----------------
// 4 rows per CTA, 256 threads; intermediate h1 lives in smem only.
__global__ void __launch_bounds__(256) k_vmlp(const float* __restrict__ A,
                                              const float* __restrict__ fw1,
                                              const float* __restrict__ fb1,
                                              const float* __restrict__ fw2,
                                              const float* __restrict__ fb2,
                                              float* __restrict__ V) {
    __shared__ __align__(16) float a_s[4][NL];
    __shared__ __align__(16) float h_s[4][NL];
    const int tid  = threadIdx.x;
    const int row0 = blockIdx.x * 4;

    for (int idx = tid; idx < 4 * NL; idx += 256)
        a_s[idx >> 8][idx & 255] = A[(row0 + (idx >> 8)) * NL + (idx & 255)];
    __syncthreads();

    float acc[4];
#pragma unroll
    for (int r = 0; r < 4; r++) acc[r] = 0.f;
    for (int k4 = 0; k4 < NL; k4 += 4) {
        float w0 = fw1[(k4 + 0) * NL + tid];
        float w1 = fw1[(k4 + 1) * NL + tid];
        float w2 = fw1[(k4 + 2) * NL + tid];
        float w3 = fw1[(k4 + 3) * NL + tid];
#pragma unroll
        for (int r = 0; r < 4; r++) {
            float4 a = *reinterpret_cast<const float4*>(&a_s[r][k4]);
            acc[r] = fmaf(a.x, w0, acc[r]);
            acc[r] = fmaf(a.y, w1, acc[r]);
            acc[r] = fmaf(a.z, w2, acc[r]);
            acc[r] = fmaf(a.w, w3, acc[r]);
        }
    }
    float b1 = fb1[tid];
#pragma unroll
    for (int r = 0; r < 4; r++) h_s[r][tid] = fmaxf(acc[r] + b1, 0.f);
    __syncthreads();

#pragma unroll
    for (int r = 0; r < 4; r++) acc[r] = 0.f;
    for (int k4 = 0; k4 < NL; k4 += 4) {
        float w0 = fw2[(k4 + 0) * NHD + tid];
        float w1 = fw2[(k4 + 1) * NHD + tid];
        float w2 = fw2[(k4 + 2) * NHD + tid];
        float w3 = fw2[(k4 + 3) * NHD + tid];
#pragma unroll
        for (int r = 0; r < 4; r++) {
            float4 a = *reinterpret_cast<const float4*>(&h_s[r][k4]);
            acc[r] = fmaf(a.x, w0, acc[r]);
            acc[r] = fmaf(a.y, w1, acc[r]);
            acc[r] = fmaf(a.z, w2, acc[r]);
            acc[r] = fmaf(a.w, w3, acc[r]);
        }
    }
    float b2 = fb2[tid];
#pragma unroll
    for (int r = 0; r < 4; r++) V[(row0 + r) * NHD + tid] = acc[r] + b2;
}

// ---------------- fused output heads ----------------
__global__ void __launch_bounds__(NOUT) k_out(const float* __restrict__ hq,
                                              const float* __restrict__ var,
                                              const float* __restrict__ ow,
                                              const float* __restrict__ ob,
                                              const float* __restrict__ vw,
                                              const float* __restrict__ vb,
                                              float* __restrict__ out) {
    __shared__ __align__(16) float a_s[8][NL];
    const int tid  = threadIdx.x;
    const int row0 = blockIdx.x * 8;
    const int sel  = blockIdx.y;
    const float* A    = sel ? var : hq;
    const float* W    = sel ? vw  : ow;
    const float* bias = sel ? vb  : ob;
    float* C = out + (sel ? (size_t)NB * NQ * NOUT : 0);

    for (int idx = tid; idx < 8 * NL; idx += NOUT)
        a_s[idx >> 8][idx & 255] = A[(row0 + (idx >> 8)) * NL + (idx & 255)];
    __syncthreads();

    float acc[8];
#pragma unroll
    for (int r = 0; r < 8; r++) acc[r] = 0.f;

    for (int k4 = 0; k4 < NL; k4 += 4) {
        float w0 = W[(k4 + 0) * NOUT + tid];
        float w1 = W[(k4 + 1) * NOUT + tid];
        float w2 = W[(k4 + 2) * NOUT + tid];
        float w3 = W[(k4 + 3) * NOUT + tid];
#pragma unroll
        for (int r = 0; r < 8; r++) {
            float4 a = *reinterpret_cast<const float4*>(&a_s[r][k4]);
            acc[r] = fmaf(a.x, w0, acc[r]);
            acc[r] = fmaf(a.y, w1, acc[r]);
            acc[r] = fmaf(a.z, w2, acc[r]);
            acc[r] = fmaf(a.w, w3, acc[r]);
        }
    }
    float bb = bias[tid];
#pragma unroll
    for (int r = 0; r < 8; r++) {
        float v = acc[r] + bb;
        if (sel) v = fmaxf(v, 0.f) + log1pf(expf(-fabsf(v)));
        C[(row0 + r) * NOUT + tid] = v;
    }
}

// ---------------- logits: delta MLP + RBF, fused (2x2 reg tile + f32x2 heads) ----------------
// __launch_bounds__(256,4): cap regs at 64 so all 512 CTAs are co-resident (no tail wave).
__global__ void __launch_bounds__(256, 4) k_logits(const float* __restrict__ pos_obs,
                                                   const float* __restrict__ pos_query,
                                                   const float* __restrict__ kw2,
                                                   const float* __restrict__ kb2,
                                                   const float* __restrict__ log_sigma) {
    __shared__ __align__(16) float kw2_s[NL * NH];   // 8 KB
    __shared__ float aq_s[KC * 34];
    __shared__ float ao_s[KC * 34];
    __shared__ float pq_s[32][3], po_s[32][3];
    __shared__ float inv_s2[NH], kb2_s[NH];

    const int tid = threadIdx.x;
    const int o0  = blockIdx.x * 32;
    const int q0  = blockIdx.y * 32;
    const int b   = blockIdx.z;
    const int ol  = tid & 15;
    const int ql  = tid >> 4;

    for (int idx = tid; idx < NL * NH; idx += 256) kw2_s[idx] = kw2[idx];
    if (tid < 96) {
        pq_s[tid / 3][tid % 3] = pos_query[(b * NQ + q0) * 3 + tid];
    } else if (tid < 192) {
        int t = tid - 96;
        po_s[t / 3][t % 3] = pos_obs[(b * NO + o0) * 3 + t];
    } else if (tid < 200) {
        int h = tid - 192;
        float s   = expf(log_sigma[h]);
        inv_s2[h] = 1.f / (s * s + 1e-6f);
        kb2_s[h]  = kb2[h];
    }

    u64 acc[4][4];
#pragma unroll
    for (int p = 0; p < 4; p++)
#pragma unroll
        for (int j = 0; j < 4; j++) acc[p][j] = 0ULL;

    const float* aqg = g_aq + (size_t)(b * NQ + q0) * NL;
    const float* aog = g_ao + (size_t)(b * NO + o0) * NL;

    for (int kc = 0; kc < NL; kc += KC) {
        __syncthreads();
        for (int idx = tid; idx < (KC / 2) * 32; idx += 256) {
            int kk2 = (idx & 31) * 2, rr = idx >> 5;
            float2 va = *reinterpret_cast<const float2*>(aqg + rr * NL + kc + kk2);
            aq_s[kk2 * 34 + rr]       = va.x;
            aq_s[(kk2 + 1) * 34 + rr] = va.y;
            float2 vo = *reinterpret_cast<const float2*>(aog + rr * NL + kc + kk2);
            ao_s[kk2 * 34 + rr]       = vo.x;
            ao_s[(kk2 + 1) * 34 + rr] = vo.y;
        }
        __syncthreads();

#pragma unroll 4
        for (int kk = 0; kk < KC; kk++) {
            float2 aq2 = *reinterpret_cast<const float2*>(&aq_s[kk * 34 + 2 * ql]);
            float2 ao2 = *reinterpret_cast<const float2*>(&ao_s[kk * 34 + 2 * ol]);
            float h00 = fmaxf(aq2.x + ao2.x, 0.f);
            float h01 = fmaxf(aq2.x + ao2.y, 0.f);
            float h10 = fmaxf(aq2.y + ao2.x, 0.f);
            float h11 = fmaxf(aq2.y + ao2.y, 0.f);
            u64 d00 = pack_dup(h00), d01 = pack_dup(h01);
            u64 d10 = pack_dup(h10), d11 = pack_dup(h11);
            const ulonglong2* wp = reinterpret_cast<const ulonglong2*>(kw2_s + (kc + kk) * 8);
            ulonglong2 wA = wp[0], wB = wp[1];
            fma2(acc[0][0], d00, wA.x); fma2(acc[0][1], d00, wA.y);
            fma2(acc[0][2], d00, wB.x); fma2(acc[0][3], d00, wB.y);
            fma2(acc[1][0], d01, wA.x); fma2(acc[1][1], d01, wA.y);
            fma2(acc[1][2], d01, wB.x); fma2(acc[1][3], d01, wB.y);
            fma2(acc[2][0], d10, wA.x); fma2(acc[2][1], d10, wA.y);
            fma2(acc[2][2], d10, wB.x); fma2(acc[2][3], d10, wB.y);
            fma2(acc[3][0], d11, wA.x); fma2(acc[3][1], d11, wA.y);
            fma2(acc[3][2], d11, wB.x); fma2(acc[3][3], d11, wB.y);
        }
    }

    const int oA = o0 + 2 * ol;
    const float pax = po_s[2 * ol][0],     pay = po_s[2 * ol][1],     paz = po_s[2 * ol][2];
    const float pbx = po_s[2 * ol + 1][0], pby = po_s[2 * ol + 1][1], pbz = po_s[2 * ol + 1][2];

#pragma unroll
    for (int qi = 0; qi < 2; qi++) {
        int q = q0 + 2 * ql + qi;
        float px = pq_s[2 * ql + qi][0], py = pq_s[2 * ql + qi][1], pz = pq_s[2 * ql + qi][2];
        float dxA = px - pax, dyA = py - pay, dzA = pz - paz;
        float dxB = px - pbx, dyB = py - pby, dzB = pz - pbz;
        float d2A = dxA * dxA + dyA * dyA + dzA * dzA;
        float d2B = dxB * dxB + dyB * dyB + dzB * dzB;
        float* orow = g_logits + ((size_t)(b * NH) * NQ + q) * NO + oA;
#pragma unroll
        for (int hp = 0; hp < 4; hp++) {
            float2 vA = unpack2(acc[qi * 2 + 0][hp]);
            float2 vB = unpack2(acc[qi * 2 + 1][hp]);
#pragma unroll
            for (int hl = 0; hl < 2; hl++) {
                int h = 2 * hp + hl;
                float va  = hl ? vA.y : vA.x;
                float vbb = hl ? vB.y : vB.x;
                float lgA = logf(expf(-d2A * inv_s2[h]) + 1e-8f) + va  + kb2_s[h];
                float lgB = logf(expf(-d2B * inv_s2[h]) + 1e-8f) + vbb + kb2_s[h];
                *reinterpret_cast<float2*>(orow + (size_t)h * NQ * NO) = make_float2(lgA, lgB);
            }
        }
    }
}

// ---------------- softmax + weighted mean/var (f32x2 over d-pairs) ----------------
__global__ void __launch_bounds__(256) k_attn() {
    __shared__ float w_s[16][WP];    // padded pitch: conflict-free row access
    const int bid = blockIdx.x;
    const int qt = bid & 31, h = (bid >> 5) & 7, b = bid >> 8;
    const int q0 = qt * 16;
    const int tid = threadIdx.x, lane = tid & 31, warp = tid >> 5;

    const float* lbase = g_logits + (size_t)(b * NH + h) * NQ * NO;
    for (int r = warp; r < 16; r += 8) {
        const float* lp = lbase + (size_t)(q0 + r) * NO;
        float vals[16];
        float mx = -3.0e38f;
#pragma unroll
        for (int j = 0; j < 16; j++) {
            vals[j] = lp[lane + j * 32];
            mx = fmaxf(mx, vals[j]);
        }
#pragma unroll
        for (int s = 16; s > 0; s >>= 1) mx = fmaxf(mx, __shfl_xor_sync(0xffffffffu, mx, s));
        float sum = 0.f;
#pragma unroll
        for (int j = 0; j < 16; j++) { vals[j] = expf(vals[j] - mx); sum += vals[j]; }
#pragma unroll
        for (int s = 16; s > 0; s >>= 1) sum += __shfl_xor_sync(0xffffffffu, sum, s);
        float inv = 1.f / sum;
#pragma unroll
        for (int j = 0; j < 16; j++) w_s[r][lane + j * 32] = vals[j] * inv;
    }
    __syncthreads();

    // phase 2: thread = (row r, d-pair dp). mean/E2 accumulated as packed f32x2.
    const int dp = tid & 15;     // d = 2*dp, 2*dp+1
    const int r  = tid >> 4;     // row 0..15
    const float* vp = g_v + (size_t)(b * NO) * NHD + h * ND + 2 * dp;
    u64 m = 0ULL, e = 0ULL;
#pragma unroll 4
    for (int o = 0; o < NO; o++) {
        float2 v2 = *reinterpret_cast<const float2*>(vp + (size_t)o * NHD);
        u64 vv = pack2(v2.x, v2.y);
        u64 sq = mul2(vv, vv);
        u64 wd = pack_dup(w_s[r][o]);
        fma2(m, vv, wd);
        fma2(e, sq, wd);
    }
    float2 mm = unpack2(m), ee = unpack2(e);
    size_t base = (size_t)(b * NQ + q0 + r) * NHD + h * ND + 2 * dp;
    *reinterpret_cast<float2*>(g_hq  + base) = mm;
    *reinterpret_cast<float2*>(g_var + base) =
        make_float2(ee.x - mm.x * mm.x, ee.y - mm.y * mm.y);
}

// ---------------- launcher ----------------
extern "C" void kernel_launch(void* const* d_in, const int* in_sizes, int n_in,
                              void* d_out, int out_size) {
    const float* h_obs     = (const float*)d_in[0];
    const float* pos_obs   = (const float*)d_in[1];
    const float* pos_query = (const float*)d_in[2];
    const float* fw1       = (const float*)d_in[3];
    const float* fb1       = (const float*)d_in[4];
    const float* fw2       = (const float*)d_in[5];
    const float* fb2       = (const float*)d_in[6];
    const float* log_sigma = (const float*)d_in[7];
    const float* kw1       = (const float*)d_in[8];
    const float* kb1       = (const float*)d_in[9];
    const float* kw2       = (const float*)d_in[10];
    const float* kb2       = (const float*)d_in[11];
    const float* ow        = (const float*)d_in[12];
    const float* ob        = (const float*)d_in[13];
    const float* vw        = (const float*)d_in[14];
    const float* vb        = (const float*)d_in[15];
    float* out = (float*)d_out;

    float *p_v, *p_hq, *p_var;
    cudaGetSymbolAddress((void**)&p_v,   g_v);
    cudaGetSymbolAddress((void**)&p_hq,  g_hq);
    cudaGetSymbolAddress((void**)&p_var, g_var);

    // position projections for the factored key-MLP
    k_posproj<<<NB * (NQ + NO), NL>>>(pos_obs, pos_query, kw1, kb1);

    // fused value MLP
    k_vmlp<<<NB * NO / 4, 256>>>(h_obs, fw1, fb1, fw2, fb2, p_v);

    // logits = log(rbf+1e-8) + delta
    dim3 glog(NO / 32, NQ / 32, NB);
    k_logits<<<glog, 256>>>(pos_obs, pos_query, kw2, kb2, log_sigma);

    // softmax + weighted mean / variance
    k_attn<<<NB * NH * (NQ / 16), 256>>>();

    // fused output heads
    dim3 gout(NB * NQ / 8, 2);
    k_out<<<gout, NOUT>>>(p_hq, p_var, ow, ob, vw, vb, out);
}